// round 12
// baseline (speedup 1.0000x reference)
#include <cuda_runtime.h>

#define NN      50000
#define NEMAX   800000
#define D       128
#define SCAN_B  512
#define MAXBLK  128

// ---------------- scratch (static device globals; no runtime alloc) ----------
// NOTE: g_count relies on (a) zero-init at module load, (b) k_nodescan
// re-zeroing each element after reading it -> zero at entry of EVERY call.
__device__ __align__(16) float g_v1[D];
__device__ __align__(16) float g_v2[D];
__device__ float g_C;
__device__ float g_p1[NN];
__device__ float g_p2[NN];
__device__ int   g_count[NN];
__device__ int   g_off[NN + 1];
__device__ int   g_woff[NN];
__device__ int   g_bsum[MAXBLK];
__device__ unsigned long long g_spack[NEMAX];      // {src:hi32, attn:lo32}

// packed f32x2 helpers (register-only; no memory-space asm)
__device__ __forceinline__ unsigned long long f2pack(float lo, float hi) {
    unsigned long long r;
    asm("mov.b64 %0, {%1, %2};" : "=l"(r) : "f"(lo), "f"(hi));
    return r;
}
__device__ __forceinline__ void ffma2(unsigned long long& acc,
                                      unsigned long long a, unsigned long long b) {
    asm("fma.rn.f32x2 %0, %1, %2, %0;" : "+l"(acc) : "l"(a), "l"(b));
}

// ---------------- K1: histogram of dst (4 edges/thread) + prep (block 0) -----
__global__ void k_front(const int* __restrict__ edges, int ne, int n,
                        const float* __restrict__ W, const float* __restrict__ wb,
                        const float* __restrict__ aw, const float* __restrict__ ab) {
    int e0 = (blockIdx.x * blockDim.x + threadIdx.x) * 4;
    if (e0 < ne) {
        if (e0 + 4 <= ne && (ne & 3) == 0) {
            int4 d4 = *(const int4*)&edges[e0];
            if ((unsigned)d4.x < (unsigned)n) atomicAdd(&g_count[d4.x], 1);
            if ((unsigned)d4.y < (unsigned)n) atomicAdd(&g_count[d4.y], 1);
            if ((unsigned)d4.z < (unsigned)n) atomicAdd(&g_count[d4.z], 1);
            if ((unsigned)d4.w < (unsigned)n) atomicAdd(&g_count[d4.w], 1);
        } else {
            for (int e = e0; e < ne && e < e0 + 4; e++) {
                int dst = edges[e];
                if ((unsigned)dst < (unsigned)n) atomicAdd(&g_count[dst], 1);
            }
        }
    }
    // prep: v1 = W^T a1, v2 = W^T a2, C = b.(a1+a2) + a_bias
    if (blockIdx.x == 0 && threadIdx.x < D) {
        int k = threadIdx.x;
        float v1 = 0.f, v2 = 0.f;
#pragma unroll 4
        for (int j = 0; j < D; j++) {
            float w = W[j * D + k];
            v1 += w * aw[j];
            v2 += w * aw[D + j];
        }
        g_v1[k] = v1;
        g_v2[k] = v2;
        if (k == 0) {
            float c = ab[0];
            for (int j = 0; j < D; j++) c += wb[j] * (aw[j] + aw[D + j]);
            g_C = c;
        }
    }
}

// ---------------- K2: node p1/p2 (warp per node) + per-block scan (b < nblk) -
__global__ void __launch_bounds__(SCAN_B) k_nodescan(
    const float4* __restrict__ emb4, int n, int nblk) {
    __shared__ int sh[SCAN_B];
    int t = threadIdx.x;

    // node part: 16 warps -> 16 nodes per block
    int w = blockIdx.x * 16 + (t >> 5);
    if (w < n) {
        int lane = t & 31;
        float4 e  = emb4[w * 32 + lane];
        float4 a1 = *(const float4*)&g_v1[lane * 4];
        float4 a2 = *(const float4*)&g_v2[lane * 4];
        float d1 = e.x * a1.x + e.y * a1.y + e.z * a1.z + e.w * a1.w;
        float d2 = e.x * a2.x + e.y * a2.y + e.z * a2.z + e.w * a2.w;
#pragma unroll
        for (int o = 16; o; o >>= 1) {
            d1 += __shfl_xor_sync(0xffffffffu, d1, o);
            d2 += __shfl_xor_sync(0xffffffffu, d2, o);
        }
        if (lane == 0) {
            g_p1[w] = d1;
            g_p2[w] = d2;
        }
    }

    // scan part: blocks < nblk scan a 512-tile of counts, then restore zeros
    if (blockIdx.x < (unsigned)nblk) {
        int i = blockIdx.x * SCAN_B + t;
        int c = (i < n) ? g_count[i] : 0;
        if (i < n) g_count[i] = 0;          // self-restoring invariant
        sh[t] = c;
        __syncthreads();
        for (int d = 1; d < SCAN_B; d <<= 1) {
            int v = (t >= d) ? sh[t - d] : 0;
            __syncthreads();
            sh[t] += v;
            __syncthreads();
        }
        if (i < n) g_off[i] = sh[t] - c;    // exclusive within block
        if (t == SCAN_B - 1) g_bsum[blockIdx.x] = sh[t];
    }
}

// ---------------- K3: fused lookback + finalize ------------------------------
__global__ void k_scan3(int n, int nblk) {
    __shared__ int pre[MAXBLK];
    int t = threadIdx.x;
    if (t < MAXBLK) pre[t] = (t < nblk) ? g_bsum[t] : 0;
    __syncthreads();
    for (int d = 1; d < MAXBLK; d <<= 1) {
        int v = (t >= d && t < MAXBLK) ? pre[t - d] : 0;
        __syncthreads();
        if (t < MAXBLK) pre[t] += v;
        __syncthreads();
    }
    int b = blockIdx.x;
    int base = (b == 0) ? 0 : pre[b - 1];
    int i = b * SCAN_B + t;
    if (i < n) {
        int o = g_off[i] + base;
        g_off[i]  = o;
        g_woff[i] = o;
    }
    if (i == 0) g_off[n] = pre[nblk - 1];
}

// ---------------- K4: attn + scatter edges sorted by dst (4 edges/thread) ----
__device__ __forceinline__ void scat1(int dst, int src, int n) {
    if ((unsigned)dst >= (unsigned)n || (unsigned)src >= (unsigned)n) return;
    float sc = g_p1[dst] + g_p2[src] + g_C;
    sc = sc > 0.f ? sc : 0.2f * sc;
    float attn = __expf(sc);
    int pos = atomicAdd(&g_woff[dst], 1);
    g_spack[pos] = ((unsigned long long)(unsigned)src << 32) | (unsigned long long)__float_as_uint(attn);
}

__global__ void k_scatter(const int* __restrict__ edges, int ne, int n) {
    int e0 = (blockIdx.x * blockDim.x + threadIdx.x) * 4;
    if (e0 >= ne) return;
    if (e0 + 4 <= ne && (ne & 3) == 0) {
        int4 d4 = *(const int4*)&edges[e0];
        int4 s4 = *(const int4*)&edges[ne + e0];
        scat1(d4.x, s4.x, n);
        scat1(d4.y, s4.y, n);
        scat1(d4.z, s4.z, n);
        scat1(d4.w, s4.w, n);
    } else {
        for (int e = e0; e < ne && e < e0 + 4; e++)
            scat1(edges[e], edges[ne + e], n);
    }
}

// ---------------- K5: fused aggregation + [emb|agg] @ T^T + bias + LN --------
// Block: 512 threads = 32 lanes (jg) x 16 warps (ig); 64 nodes/block.
// Warp ig owns nodes nb+4*ig..+3. Phase A aggregates neighbors into registers
// (aggR) and holds emb rows (embR), lane l = columns 4l..4l+3. Phase B stages
// each 64-k X panel from registers into Xt smem, then: 1 conflict-free
// LDS.128 (Tt) + 1 broadcast LDS.128 (Xt) + 8 FFMA2 per k. 64 nodes/block
// halves per-chip T panel traffic vs 32-node blocks.
#define TT_STR 132
#define XT_STR 68

__global__ void __launch_bounds__(512) k_epi(
    const float4* __restrict__ emb4,
    const float*  __restrict__ T,
    const float*  __restrict__ tb,
    const float*  __restrict__ gamma,
    const float*  __restrict__ beta,
    float*        __restrict__ out, int n)
{
    __shared__ __align__(16) float Tt[64 * TT_STR];   // 33792 B
    __shared__ __align__(16) float Xt[64 * XT_STR];   // 17408 B

    int tid = threadIdx.x;
    int jg  = tid & 31;        // lane
    int ig  = tid >> 5;        // warp -> node group (i = 4*ig + c), 0..15
    int nb  = blockIdx.x * 64;
    const float4* T4 = (const float4*)T;

    // ---- phase A: per-warp emb rows + neighbor aggregation (registers) ------
    float4 embR[4], aggR[4];
#pragma unroll
    for (int c = 0; c < 4; c++) {
        int node = nb + 4 * ig + c;
        if (node < n) {
            embR[c] = emb4[node * 32 + jg];
            int beg = g_off[node], end = g_off[node + 1];
            float ax = 0.f, ay = 0.f, az = 0.f, aw = 0.f, den = 0.f;
            for (int base = beg; base < end; base += 32) {
                int m = end - base;
                if (m > 32) m = 32;
                unsigned long long pk = (jg < m) ? g_spack[base + jg] : 0ULL;
#pragma unroll 4
                for (int t = 0; t < m; t++) {
                    unsigned long long p = __shfl_sync(0xffffffffu, pk, t);
                    float a = __uint_as_float((unsigned)p);
                    int   s = (int)(p >> 32);
                    float4 v = emb4[s * 32 + jg];
                    ax += a * v.x; ay += a * v.y; az += a * v.z; aw += a * v.w;
                    den += a;
                }
            }
            float sc1 = 1.0f / (den + 1e-20f);
            aggR[c] = make_float4(ax * sc1, ay * sc1, az * sc1, aw * sc1);
        } else {
            embR[c] = make_float4(0.f, 0.f, 0.f, 0.f);
            aggR[c] = make_float4(0.f, 0.f, 0.f, 0.f);
        }
    }

    // ---- phase B: GEMM over 4 panels of 64 k --------------------------------
    unsigned long long acc2[8];
#pragma unroll
    for (int q = 0; q < 8; q++) acc2[q] = 0ULL;

    for (int p = 0; p < 4; p++) {
        __syncthreads();   // prior panels fully consumed
        // T panel: rows j = 0..127, k-slice [p*64, p*64+64), stored transposed
        for (int it = tid; it < 2048; it += 512) {
            int j = it >> 4, k4 = it & 15;
            float4 v = T4[j * 64 + p * 16 + k4];
            int kr = k4 * 4;
            Tt[(kr + 0) * TT_STR + j] = v.x;
            Tt[(kr + 1) * TT_STR + j] = v.y;
            Tt[(kr + 2) * TT_STR + j] = v.z;
            Tt[(kr + 3) * TT_STR + j] = v.w;
        }
        // X panel from registers: lanes [16*(p&1), +16) hold this k-slice
        {
            int base = (p & 1) * 16;
            int jl = jg - base;                 // 0..15 when active
            if (jl >= 0 && jl < 16) {
                int kr = jl * 4;
#pragma unroll
                for (int c = 0; c < 4; c++) {
                    float4 v = (p < 2) ? embR[c] : aggR[c];
                    int i = 4 * ig + c;
                    Xt[(kr + 0) * XT_STR + i] = v.x;
                    Xt[(kr + 1) * XT_STR + i] = v.y;
                    Xt[(kr + 2) * XT_STR + i] = v.z;
                    Xt[(kr + 3) * XT_STR + i] = v.w;
                }
            }
        }
        __syncthreads();

        const float4* Tt4 = (const float4*)Tt;   // row stride 33 float4
        const float4* Xt4 = (const float4*)Xt;   // row stride 17 float4
#pragma unroll 4
        for (int k = 0; k < 64; k++) {
            float4 t = Tt4[k * 33 + jg];   // T[4jg+0..3][k]
            float4 x = Xt4[k * 17 + ig];   // X[4ig+0..3][k]  (broadcast)
            unsigned long long tA = f2pack(t.x, t.y);
            unsigned long long tB = f2pack(t.z, t.w);
            unsigned long long xA = f2pack(x.x, x.x);
            unsigned long long xB = f2pack(x.y, x.y);
            unsigned long long xC = f2pack(x.z, x.z);
            unsigned long long xD = f2pack(x.w, x.w);
            ffma2(acc2[0], tA, xA); ffma2(acc2[1], tB, xA);
            ffma2(acc2[2], tA, xB); ffma2(acc2[3], tB, xB);
            ffma2(acc2[4], tA, xC); ffma2(acc2[5], tB, xC);
            ffma2(acc2[6], tA, xD); ffma2(acc2[7], tB, xD);
        }
    }

    __syncthreads();           // Tt reads done; reuse as h staging (64 x 132)
    float* hs = Tt;
    float b0 = tb[4 * jg + 0], b1 = tb[4 * jg + 1], b2 = tb[4 * jg + 2], b3 = tb[4 * jg + 3];
#pragma unroll
    for (int c = 0; c < 4; c++) {
        int i = 4 * ig + c;
        unsigned long long pA = acc2[c * 2 + 0], pB = acc2[c * 2 + 1];
        hs[i * TT_STR + 4 * jg + 0] = __uint_as_float((unsigned)pA) + b0;
        hs[i * TT_STR + 4 * jg + 1] = __uint_as_float((unsigned)(pA >> 32)) + b1;
        hs[i * TT_STR + 4 * jg + 2] = __uint_as_float((unsigned)pB) + b2;
        hs[i * TT_STR + 4 * jg + 3] = __uint_as_float((unsigned)(pB >> 32)) + b3;
    }
    __syncthreads();

    // LayerNorm: warp ig handles nodes 4*ig..4*ig+3
    int lane = jg;
#pragma unroll
    for (int q = 0; q < 4; q++) {
        int i = ig * 4 + q;
        int node = nb + i;
        float4 v = *(const float4*)&hs[i * TT_STR + lane * 4];
        float s  = v.x + v.y + v.z + v.w;
        float ss = v.x * v.x + v.y * v.y + v.z * v.z + v.w * v.w;
#pragma unroll
        for (int o = 16; o; o >>= 1) {
            s  += __shfl_xor_sync(0xffffffffu, s,  o);
            ss += __shfl_xor_sync(0xffffffffu, ss, o);
        }
        float mu  = s * (1.0f / 128.0f);
        float var = ss * (1.0f / 128.0f) - mu * mu;
        float rs  = rsqrtf(var + 1e-5f);
        if (node < n) {
            float4 g  = *(const float4*)&gamma[lane * 4];
            float4 bb = *(const float4*)&beta[lane * 4];
            float4 o4;
            o4.x = (v.x - mu) * rs * g.x + bb.x;
            o4.y = (v.y - mu) * rs * g.y + bb.y;
            o4.z = (v.z - mu) * rs * g.z + bb.z;
            o4.w = (v.w - mu) * rs * g.w + bb.w;
            *(float4*)&out[node * 128 + lane * 4] = o4;
        }
    }
}

// ---------------- launch -----------------------------------------------------
extern "C" void kernel_launch(void* const* d_in, const int* in_sizes, int n_in,
                              void* d_out, int out_size) {
    const float* emb   = (const float*)d_in[0];
    const int*   edges = (const int*)d_in[1];       // int64 downcast to int32 by harness
    const float* W     = (const float*)d_in[2];
    const float* wb    = (const float*)d_in[3];
    const float* aw    = (const float*)d_in[4];
    const float* ab    = (const float*)d_in[5];
    const float* T     = (const float*)d_in[6];
    const float* tbias = (const float*)d_in[7];
    const float* gam   = (const float*)d_in[8];
    const float* bet   = (const float*)d_in[9];
    float* out = (float*)d_out;

    int n  = in_sizes[0] / D;   // nodes
    int ne = in_sizes[1] / 2;   // edges
    int nblk = (n + SCAN_B - 1) / SCAN_B;           // <= 98 for n=50000
    int ne4  = (ne + 3) / 4;
    int nsblk = (n + 15) / 16;                      // node+scan grid (>= nblk)

    k_front   <<<(ne4 + 255) / 256, 256>>>(edges, ne, n, W, wb, aw, ab);
    k_nodescan<<<nsblk, SCAN_B>>>((const float4*)emb, n, nblk);
    k_scan3   <<<nblk, SCAN_B>>>(n, nblk);
    k_scatter <<<(ne4 + 255) / 256, 256>>>(edges, ne, n);
    k_epi     <<<(n + 63) / 64, 512>>>((const float4*)emb, T, tbias, gam, bet, out, n);
}

// round 13
// speedup vs baseline: 1.0562x; 1.0562x over previous
#include <cuda_runtime.h>

#define NN      50000
#define NEMAX   800000
#define D       128
#define SCAN_B  512

// ---------------- scratch (static device globals; no runtime alloc) ----------
// g_count invariant: zero at entry of every kernel_launch call.
// (a) zero-init at module load; (b) k_epi re-zeroes it at the end of each call.
__device__ __align__(16) float g_v1[D];
__device__ __align__(16) float g_v2[D];
__device__ float g_C;
__device__ float g_p1[NN];
__device__ float g_p2[NN];
__device__ int   g_count[NN];
__device__ int   g_off[NN + 1];
__device__ int   g_woff[NN];
__device__ unsigned long long g_spack[NEMAX];      // {src:hi32, attn:lo32}

// packed f32x2 helpers (register-only; no memory-space asm)
__device__ __forceinline__ unsigned long long f2pack(float lo, float hi) {
    unsigned long long r;
    asm("mov.b64 %0, {%1, %2};" : "=l"(r) : "f"(lo), "f"(hi));
    return r;
}
__device__ __forceinline__ void ffma2(unsigned long long& acc,
                                      unsigned long long a, unsigned long long b) {
    asm("fma.rn.f32x2 %0, %1, %2, %0;" : "+l"(acc) : "l"(a), "l"(b));
}

// ---------------- K1: histogram of dst (4 edges/thread) + prep (block 0) -----
__global__ void k_front(const int* __restrict__ edges, int ne, int n,
                        const float* __restrict__ W, const float* __restrict__ wb,
                        const float* __restrict__ aw, const float* __restrict__ ab) {
    int e0 = (blockIdx.x * blockDim.x + threadIdx.x) * 4;
    if (e0 < ne) {
        if (e0 + 4 <= ne && (ne & 3) == 0) {
            int4 d4 = *(const int4*)&edges[e0];
            if ((unsigned)d4.x < (unsigned)n) atomicAdd(&g_count[d4.x], 1);
            if ((unsigned)d4.y < (unsigned)n) atomicAdd(&g_count[d4.y], 1);
            if ((unsigned)d4.z < (unsigned)n) atomicAdd(&g_count[d4.z], 1);
            if ((unsigned)d4.w < (unsigned)n) atomicAdd(&g_count[d4.w], 1);
        } else {
            for (int e = e0; e < ne && e < e0 + 4; e++) {
                int dst = edges[e];
                if ((unsigned)dst < (unsigned)n) atomicAdd(&g_count[dst], 1);
            }
        }
    }
    // prep: v1 = W^T a1, v2 = W^T a2, C = b.(a1+a2) + a_bias
    if (blockIdx.x == 0 && threadIdx.x < D) {
        int k = threadIdx.x;
        float v1 = 0.f, v2 = 0.f;
#pragma unroll 4
        for (int j = 0; j < D; j++) {
            float w = W[j * D + k];
            v1 += w * aw[j];
            v2 += w * aw[D + j];
        }
        g_v1[k] = v1;
        g_v2[k] = v2;
        if (k == 0) {
            float c = ab[0];
            for (int j = 0; j < D; j++) c += wb[j] * (aw[j] + aw[D + j]);
            g_C = c;
        }
    }
}

// ---------------- K2: node p1/p2 (warp/node) + FULL scan (redundant base) ----
// Blocks < nblk additionally produce final g_off/g_woff for their 512-tile:
// base = sum of ALL counts before the tile (read directly — no lookback kernel),
// then in-block Hillis-Steele scan. g_count is NOT modified here (k_epi zeroes).
__global__ void __launch_bounds__(SCAN_B) k_midscan(
    const float4* __restrict__ emb4, int n, int nblk) {
    __shared__ int sh[SCAN_B];
    __shared__ int red[SCAN_B / 32];
    int t = threadIdx.x;

    // node part: 16 warps -> 16 nodes per block
    int w = blockIdx.x * 16 + (t >> 5);
    if (w < n) {
        int lane = t & 31;
        float4 e  = emb4[w * 32 + lane];
        float4 a1 = *(const float4*)&g_v1[lane * 4];
        float4 a2 = *(const float4*)&g_v2[lane * 4];
        float d1 = e.x * a1.x + e.y * a1.y + e.z * a1.z + e.w * a1.w;
        float d2 = e.x * a2.x + e.y * a2.y + e.z * a2.z + e.w * a2.w;
#pragma unroll
        for (int o = 16; o; o >>= 1) {
            d1 += __shfl_xor_sync(0xffffffffu, d1, o);
            d2 += __shfl_xor_sync(0xffffffffu, d2, o);
        }
        if (lane == 0) {
            g_p1[w] = d1;
            g_p2[w] = d2;
        }
    }

    if (blockIdx.x >= (unsigned)nblk) return;
    int b = blockIdx.x;
    int tile0 = b * SCAN_B;

    // redundant base: sum all counts before this tile
    int part = 0;
    for (int idx = t; idx < tile0; idx += SCAN_B) part += g_count[idx];
#pragma unroll
    for (int o = 16; o; o >>= 1) part += __shfl_xor_sync(0xffffffffu, part, o);
    if ((t & 31) == 0) red[t >> 5] = part;
    __syncthreads();
    int base = 0;
#pragma unroll
    for (int q = 0; q < SCAN_B / 32; q++) base += red[q];

    // in-block scan of this tile
    int i = tile0 + t;
    int c = (i < n) ? g_count[i] : 0;
    sh[t] = c;
    __syncthreads();
    for (int d = 1; d < SCAN_B; d <<= 1) {
        int v = (t >= d) ? sh[t - d] : 0;
        __syncthreads();
        sh[t] += v;
        __syncthreads();
    }
    if (i < n) {
        int o = base + sh[t] - c;           // final exclusive prefix
        g_off[i]  = o;
        g_woff[i] = o;
    }
    if (b == nblk - 1 && t == SCAN_B - 1) g_off[n] = base + sh[t];
}

// ---------------- K3: attn + scatter edges sorted by dst (4 edges/thread) ----
__device__ __forceinline__ void scat1(int dst, int src, int n) {
    if ((unsigned)dst >= (unsigned)n || (unsigned)src >= (unsigned)n) return;
    float sc = g_p1[dst] + g_p2[src] + g_C;
    sc = sc > 0.f ? sc : 0.2f * sc;
    float attn = __expf(sc);
    int pos = atomicAdd(&g_woff[dst], 1);
    g_spack[pos] = ((unsigned long long)(unsigned)src << 32) | (unsigned long long)__float_as_uint(attn);
}

__global__ void k_scatter(const int* __restrict__ edges, int ne, int n) {
    int e0 = (blockIdx.x * blockDim.x + threadIdx.x) * 4;
    if (e0 >= ne) return;
    if (e0 + 4 <= ne && (ne & 3) == 0) {
        int4 d4 = *(const int4*)&edges[e0];
        int4 s4 = *(const int4*)&edges[ne + e0];
        scat1(d4.x, s4.x, n);
        scat1(d4.y, s4.y, n);
        scat1(d4.z, s4.z, n);
        scat1(d4.w, s4.w, n);
    } else {
        for (int e = e0; e < ne && e < e0 + 4; e++)
            scat1(edges[e], edges[ne + e], n);
    }
}

// ---------------- K4: fused aggregation + [emb|agg] @ T^T + bias + LN --------
// R11-exact config: 256 threads = 32 lanes (jg) x 8 warps (ig); 32 nodes/block.
// Also re-zeroes g_count (self-restoring invariant for the next call).
#define TT_STR 132
#define XT_STR 36

__global__ void __launch_bounds__(256) k_epi(
    const float4* __restrict__ emb4,
    const float*  __restrict__ T,
    const float*  __restrict__ tb,
    const float*  __restrict__ gamma,
    const float*  __restrict__ beta,
    float*        __restrict__ out, int n)
{
    __shared__ __align__(16) float Tt[64 * TT_STR];   // 33792 B
    __shared__ __align__(16) float Xt[64 * XT_STR];   //  9216 B

    int tid = threadIdx.x;
    int jg  = tid & 31;        // lane
    int ig  = tid >> 5;        // warp -> node group (i = 4*ig + c)
    int nb  = blockIdx.x * 32;
    const float4* T4 = (const float4*)T;

    // restore g_count = 0 for the next kernel_launch call (race-free: g_count
    // is not read by scatter/epi; one guarded store per thread covers n).
    {
        int z = blockIdx.x * 256 + tid;
        if (z < n) g_count[z] = 0;
    }

    // ---- phase A: per-warp emb rows + neighbor aggregation (registers) ------
    float4 embR[4], aggR[4];
#pragma unroll
    for (int c = 0; c < 4; c++) {
        int node = nb + 4 * ig + c;
        if (node < n) {
            embR[c] = emb4[node * 32 + jg];
            int beg = g_off[node], end = g_off[node + 1];
            float ax = 0.f, ay = 0.f, az = 0.f, aw = 0.f, den = 0.f;
            for (int base = beg; base < end; base += 32) {
                int m = end - base;
                if (m > 32) m = 32;
                unsigned long long pk = (jg < m) ? g_spack[base + jg] : 0ULL;
#pragma unroll 4
                for (int t = 0; t < m; t++) {
                    unsigned long long p = __shfl_sync(0xffffffffu, pk, t);
                    float a = __uint_as_float((unsigned)p);
                    int   s = (int)(p >> 32);
                    float4 v = emb4[s * 32 + jg];
                    ax += a * v.x; ay += a * v.y; az += a * v.z; aw += a * v.w;
                    den += a;
                }
            }
            float sc1 = 1.0f / (den + 1e-20f);
            aggR[c] = make_float4(ax * sc1, ay * sc1, az * sc1, aw * sc1);
        } else {
            embR[c] = make_float4(0.f, 0.f, 0.f, 0.f);
            aggR[c] = make_float4(0.f, 0.f, 0.f, 0.f);
        }
    }

    // ---- phase B: GEMM over 4 panels of 64 k --------------------------------
    unsigned long long acc2[8];
#pragma unroll
    for (int q = 0; q < 8; q++) acc2[q] = 0ULL;

    for (int p = 0; p < 4; p++) {
        __syncthreads();   // prior panels fully consumed
        // T panel: rows j = 0..127, k-slice [p*64, p*64+64), stored transposed
        for (int it = tid; it < 2048; it += 256) {
            int j = it >> 4, k4 = it & 15;
            float4 v = T4[j * 64 + p * 16 + k4];
            int kr = k4 * 4;
            Tt[(kr + 0) * TT_STR + j] = v.x;
            Tt[(kr + 1) * TT_STR + j] = v.y;
            Tt[(kr + 2) * TT_STR + j] = v.z;
            Tt[(kr + 3) * TT_STR + j] = v.w;
        }
        // X panel from registers: lanes [16*(p&1), +16) hold this k-slice
        {
            int base = (p & 1) * 16;
            int jl = jg - base;                 // 0..15 when active
            if (jl >= 0 && jl < 16) {
                int kr = jl * 4;
#pragma unroll
                for (int c = 0; c < 4; c++) {
                    float4 v = (p < 2) ? embR[c] : aggR[c];
                    int i = 4 * ig + c;
                    Xt[(kr + 0) * XT_STR + i] = v.x;
                    Xt[(kr + 1) * XT_STR + i] = v.y;
                    Xt[(kr + 2) * XT_STR + i] = v.z;
                    Xt[(kr + 3) * XT_STR + i] = v.w;
                }
            }
        }
        __syncthreads();

        const float4* Tt4 = (const float4*)Tt;   // row stride 33 float4
        const float4* Xt4 = (const float4*)Xt;   // row stride  9 float4
#pragma unroll 4
        for (int k = 0; k < 64; k++) {
            float4 t = Tt4[k * 33 + jg];   // T[4jg+0..3][k]
            float4 x = Xt4[k * 9 + ig];    // X[4ig+0..3][k]  (broadcast)
            unsigned long long tA = f2pack(t.x, t.y);
            unsigned long long tB = f2pack(t.z, t.w);
            unsigned long long xA = f2pack(x.x, x.x);
            unsigned long long xB = f2pack(x.y, x.y);
            unsigned long long xC = f2pack(x.z, x.z);
            unsigned long long xD = f2pack(x.w, x.w);
            ffma2(acc2[0], tA, xA); ffma2(acc2[1], tB, xA);
            ffma2(acc2[2], tA, xB); ffma2(acc2[3], tB, xB);
            ffma2(acc2[4], tA, xC); ffma2(acc2[5], tB, xC);
            ffma2(acc2[6], tA, xD); ffma2(acc2[7], tB, xD);
        }
    }

    __syncthreads();           // Tt reads done; reuse as h staging
    float* hs = Tt;            // 32 rows x TT_STR
    float b0 = tb[4 * jg + 0], b1 = tb[4 * jg + 1], b2 = tb[4 * jg + 2], b3 = tb[4 * jg + 3];
#pragma unroll
    for (int c = 0; c < 4; c++) {
        int i = 4 * ig + c;
        unsigned long long pA = acc2[c * 2 + 0], pB = acc2[c * 2 + 1];
        hs[i * TT_STR + 4 * jg + 0] = __uint_as_float((unsigned)pA) + b0;
        hs[i * TT_STR + 4 * jg + 1] = __uint_as_float((unsigned)(pA >> 32)) + b1;
        hs[i * TT_STR + 4 * jg + 2] = __uint_as_float((unsigned)pB) + b2;
        hs[i * TT_STR + 4 * jg + 3] = __uint_as_float((unsigned)(pB >> 32)) + b3;
    }
    __syncthreads();

    // LayerNorm: warp ig handles nodes 4*ig..4*ig+3
    int lane = jg;
#pragma unroll
    for (int q = 0; q < 4; q++) {
        int i = ig * 4 + q;
        int node = nb + i;
        float4 v = *(const float4*)&hs[i * TT_STR + lane * 4];
        float s  = v.x + v.y + v.z + v.w;
        float ss = v.x * v.x + v.y * v.y + v.z * v.z + v.w * v.w;
#pragma unroll
        for (int o = 16; o; o >>= 1) {
            s  += __shfl_xor_sync(0xffffffffu, s,  o);
            ss += __shfl_xor_sync(0xffffffffu, ss, o);
        }
        float mu  = s * (1.0f / 128.0f);
        float var = ss * (1.0f / 128.0f) - mu * mu;
        float rs  = rsqrtf(var + 1e-5f);
        if (node < n) {
            float4 g  = *(const float4*)&gamma[lane * 4];
            float4 bb = *(const float4*)&beta[lane * 4];
            float4 o4;
            o4.x = (v.x - mu) * rs * g.x + bb.x;
            o4.y = (v.y - mu) * rs * g.y + bb.y;
            o4.z = (v.z - mu) * rs * g.z + bb.z;
            o4.w = (v.w - mu) * rs * g.w + bb.w;
            *(float4*)&out[node * 128 + lane * 4] = o4;
        }
    }
}

// ---------------- launch -----------------------------------------------------
extern "C" void kernel_launch(void* const* d_in, const int* in_sizes, int n_in,
                              void* d_out, int out_size) {
    const float* emb   = (const float*)d_in[0];
    const int*   edges = (const int*)d_in[1];       // int64 downcast to int32 by harness
    const float* W     = (const float*)d_in[2];
    const float* wb    = (const float*)d_in[3];
    const float* aw    = (const float*)d_in[4];
    const float* ab    = (const float*)d_in[5];
    const float* T     = (const float*)d_in[6];
    const float* tbias = (const float*)d_in[7];
    const float* gam   = (const float*)d_in[8];
    const float* bet   = (const float*)d_in[9];
    float* out = (float*)d_out;

    int n  = in_sizes[0] / D;   // nodes
    int ne = in_sizes[1] / 2;   // edges
    int nblk  = (n + SCAN_B - 1) / SCAN_B;          // <= 98 for n=50000
    int ne4   = (ne + 3) / 4;
    int nsblk = (n + 15) / 16;                      // node+scan grid (>= nblk)

    k_front  <<<(ne4 + 255) / 256, 256>>>(edges, ne, n, W, wb, aw, ab);
    k_midscan<<<nsblk, SCAN_B>>>((const float4*)emb, n, nblk);
    k_scatter<<<(ne4 + 255) / 256, 256>>>(edges, ne, n);
    k_epi    <<<(n + 31) / 32, 256>>>((const float4*)emb, T, tbias, gam, bet, out, n);
}